// round 6
// baseline (speedup 1.0000x reference)
#include <cuda_runtime.h>
#include <cuda_fp16.h>

#define NB   8
#define NP   2048
#define C1   64
#define C2   128
#define NS   64
#define RAD2 0.36f

// Scratch: per-point MLP features f[b, n, 128] in fp16 (4 MB, L2-resident)
__device__ __half g_fh[NB * NP * C2];

// ---------------------------------------------------------------------------
// Kernel 1: per-point MLP. Block = 256 threads / 64 points. W2 transposed in
// SMEM (k-major); each warp accumulates 8 points at once (32 fp32 accs) so a
// W2 k-row LDS serves 8 points -> FFMA-pipe bound.
// ---------------------------------------------------------------------------
__global__ __launch_bounds__(256)
void mlp_kernel(const float* __restrict__ x,
                const float* __restrict__ W1,
                const float* __restrict__ b1,
                const float* __restrict__ W2,
                const float* __restrict__ b2)
{
    __shared__ float w2t[C1][C2];      // 32 KB, [k][p]
    __shared__ float h1s[64][C1];      // 16 KB
    __shared__ float xs3[64 * 3];
    __shared__ float b2s[C2];

    int tid = threadIdx.x;
    int p0  = blockIdx.x * 64;

    for (int i = tid; i < C2 * C1; i += 256) {
        int p = i >> 6, k = i & 63;
        w2t[k][p] = W2[i];
    }
    for (int i = tid; i < 64 * 3; i += 256) xs3[i] = x[p0 * 3 + i];
    if (tid < C2) b2s[tid] = b2[tid];
    __syncthreads();

    // h1 for 64 points (4096 vals / 256 threads)
    for (int i = tid; i < 64 * C1; i += 256) {
        int q = i >> 6, c = i & 63;
        float v = fmaf(W1[c * 3 + 2], xs3[q * 3 + 2],
                  fmaf(W1[c * 3 + 1], xs3[q * 3 + 1],
                  fmaf(W1[c * 3 + 0], xs3[q * 3 + 0], b1[c])));
        h1s[q][c] = fmaxf(v, 0.f);
    }
    __syncthreads();

    int warp = tid >> 5, lane = tid & 31;
    int lane4 = lane * 4;
    int q0 = warp * 8;                  // 8 points per warp
    float4 binit = *(const float4*)&b2s[lane4];

    float4 acc[8];
    #pragma unroll
    for (int p = 0; p < 8; p++) acc[p] = binit;

    #pragma unroll 4
    for (int k = 0; k < C1; k += 4) {
        float4 w0 = *(const float4*)(w2t[k + 0] + lane4);
        float4 w1 = *(const float4*)(w2t[k + 1] + lane4);
        float4 w2 = *(const float4*)(w2t[k + 2] + lane4);
        float4 w3 = *(const float4*)(w2t[k + 3] + lane4);
        #pragma unroll
        for (int p = 0; p < 8; p++) {
            float4 h = *(const float4*)(h1s[q0 + p] + k);   // broadcast LDS
            float4 a = acc[p];
            a.x = fmaf(h.x, w0.x, a.x); a.y = fmaf(h.x, w0.y, a.y);
            a.z = fmaf(h.x, w0.z, a.z); a.w = fmaf(h.x, w0.w, a.w);
            a.x = fmaf(h.y, w1.x, a.x); a.y = fmaf(h.y, w1.y, a.y);
            a.z = fmaf(h.y, w1.z, a.z); a.w = fmaf(h.y, w1.w, a.w);
            a.x = fmaf(h.z, w2.x, a.x); a.y = fmaf(h.z, w2.y, a.y);
            a.z = fmaf(h.z, w2.z, a.z); a.w = fmaf(h.z, w2.w, a.w);
            a.x = fmaf(h.w, w3.x, a.x); a.y = fmaf(h.w, w3.y, a.y);
            a.z = fmaf(h.w, w3.z, a.z); a.w = fmaf(h.w, w3.w, a.w);
            acc[p] = a;
        }
    }

    #pragma unroll
    for (int p = 0; p < 8; p++) {
        float4 v = acc[p];
        __half2 h01 = __floats2half2_rn(fmaxf(v.x, 0.f), fmaxf(v.y, 0.f));
        __half2 h23 = __floats2half2_rn(fmaxf(v.z, 0.f), fmaxf(v.w, 0.f));
        uint2 st;
        st.x = *(unsigned*)&h01;
        st.y = *(unsigned*)&h23;
        ((uint2*)(g_fh + (size_t)(p0 + q0 + p) * C2))[lane] = st;
    }
}

// ---------------------------------------------------------------------------
// Kernel 2: ball query + fp16 max-pool. Block = 8 warps, 16 centers (2 per
// warp, sequential). Gather: 2 neighbors per LDG.128 (half-warp each covers a
// full 256B f row), shfl_xor(16) to merge halves.
// ---------------------------------------------------------------------------
__global__ __launch_bounds__(256, 6)
void group_max_kernel(const float* __restrict__ x, float* __restrict__ out)
{
    __shared__ float xs[NP], ys[NP], zs[NP], sq[NP];     // 32 KB
    __shared__ unsigned short nbr[8][NS];                // 1 KB
    __shared__ float tr[8][132];                         // padded transpose buf

    int b   = blockIdx.y;
    int tid = threadIdx.x;

    const float* xb = x + b * NP * 3;
    for (int i = tid; i < NP; i += 256) {
        float a0 = xb[i * 3 + 0];
        float a1 = xb[i * 3 + 1];
        float a2 = xb[i * 3 + 2];
        xs[i] = a0; ys[i] = a1; zs[i] = a2;
        sq[i] = a0 * a0 + a1 * a1 + a2 * a2;
    }
    __syncthreads();

    int warp = tid >> 5, lane = tid & 31;
    int half = lane >> 4;       // 0/1: which neighbor of the pair
    int lo   = lane & 15;       // 16B chunk within a 256B f row
    const uint4* fb4 = (const uint4*)(g_fh + (size_t)b * NP * C2);  // 16 uint4/row

    for (int it = 0; it < 2; it++) {
        int s = blockIdx.x * 16 + it * 8 + warp;
        float cx = xs[s], cy = ys[s], cz = zs[s], cs = sq[s];

        // Scan ascending j; first <=64 with dist <= R^2 (exact ref formula)
        int cnt = 0;
        for (int j0 = 0; j0 < NP && cnt < NS; j0 += 32) {
            int j = j0 + lane;
            float d = cs + sq[j] - 2.f * (cx * xs[j] + cy * ys[j] + cz * zs[j]);
            bool ok = !(d > RAD2);
            unsigned mask = __ballot_sync(0xffffffffu, ok);
            int rank = __popc(mask & ((1u << lane) - 1u));
            if (ok && (cnt + rank) < NS)
                nbr[warp][cnt + rank] = (unsigned short)j;
            cnt += __popc(mask);
            if (cnt > NS) cnt = NS;
        }
        __syncwarp();

        // Paired gather: lanes 0-15 -> neighbor k, lanes 16-31 -> neighbor k+1
        __half2 m0 = __float2half2_rn(0.f);
        __half2 m1 = m0, m2 = m0, m3 = m0;

        int k = 0;
        for (; k + 8 <= cnt; k += 8) {
            uint4 v[4];
            #pragma unroll
            for (int u = 0; u < 4; u++) {
                int j = nbr[warp][k + u * 2 + half];
                v[u] = fb4[j * 16 + lo];
            }
            #pragma unroll
            for (int u = 0; u < 4; u++) {
                m0 = __hmax2(m0, *reinterpret_cast<__half2*>(&v[u].x));
                m1 = __hmax2(m1, *reinterpret_cast<__half2*>(&v[u].y));
                m2 = __hmax2(m2, *reinterpret_cast<__half2*>(&v[u].z));
                m3 = __hmax2(m3, *reinterpret_cast<__half2*>(&v[u].w));
            }
        }
        for (; k < cnt; k += 2) {
            int idx = k + half;
            if (idx > cnt - 1) idx = cnt - 1;   // duplicate = no-op for max
            int j = nbr[warp][idx];
            uint4 v = fb4[j * 16 + lo];
            m0 = __hmax2(m0, *reinterpret_cast<__half2*>(&v.x));
            m1 = __hmax2(m1, *reinterpret_cast<__half2*>(&v.y));
            m2 = __hmax2(m2, *reinterpret_cast<__half2*>(&v.z));
            m3 = __hmax2(m3, *reinterpret_cast<__half2*>(&v.w));
        }

        // Merge the two half-warp partials (channels lo*8 .. lo*8+7)
        #define XMAX(m) { unsigned o = __shfl_xor_sync(0xffffffffu, *(unsigned*)&m, 16); \
                          m = __hmax2(m, *reinterpret_cast<__half2*>(&o)); }
        XMAX(m0) XMAX(m1) XMAX(m2) XMAX(m3)
        #undef XMAX

        if (half == 0) {
            float2 f0 = __half22float2(m0);
            float2 f1 = __half22float2(m1);
            float2 f2 = __half22float2(m2);
            float2 f3 = __half22float2(m3);
            float* t = &tr[warp][lo * 8];
            t[0] = f0.x; t[1] = f0.y; t[2] = f1.x; t[3] = f1.y;
            t[4] = f2.x; t[5] = f2.y; t[6] = f3.x; t[7] = f3.y;
        }
        __syncthreads();

        float* ob = out + (size_t)b * C2 * NP + blockIdx.x * 16 + it * 8;
        for (int i = tid; i < C2 * 8; i += 256) {
            int si = i & 7;       // center within group of 8
            int p  = i >> 3;      // channel
            ob[p * NP + si] = tr[si][p];
        }
        __syncthreads();
    }
}

extern "C" void kernel_launch(void* const* d_in, const int* in_sizes, int n_in,
                              void* d_out, int out_size)
{
    const float* x  = (const float*)d_in[0];
    const float* W1 = (const float*)d_in[1];
    const float* b1 = (const float*)d_in[2];
    const float* W2 = (const float*)d_in[3];
    const float* b2 = (const float*)d_in[4];
    float* out = (float*)d_out;

    // Kernel 1: 64 points per block -> 256 blocks
    mlp_kernel<<<(NB * NP) / 64, 256>>>(x, W1, b1, W2, b2);

    // Kernel 2: 16 centers per block, grid (128, 8)
    dim3 grid(NP / 16, NB);
    group_max_kernel<<<grid, 256>>>(x, out);
}

// round 7
// speedup vs baseline: 1.6731x; 1.6731x over previous
#include <cuda_runtime.h>
#include <cuda_fp16.h>

#define NB   8
#define NP   2048
#define C1   64
#define C2   128
#define NS   64
#define RAD2 0.36f

// Scratch: per-point MLP features f[b, n, 128] in fp16 (4 MB, L2-resident)
__device__ __half g_fh[NB * NP * C2];

// ---------------------------------------------------------------------------
// Kernel 1: per-point MLP. Block = 256 threads / 128 points (W2 staged once
// per block). Warp accumulates 8 points per pass (2 passes) so each w2t k-row
// LDS.128 serves 8 points -> FFMA-pipe bound.
// ---------------------------------------------------------------------------
__global__ __launch_bounds__(256)
void mlp_kernel(const float* __restrict__ x,
                const float* __restrict__ W1,
                const float* __restrict__ b1,
                const float* __restrict__ W2,
                const float* __restrict__ b2)
{
    __shared__ float w2t[C1][C2];      // 32 KB, [k][p]
    __shared__ float h1s[128][C1];     // 32 KB
    __shared__ float xs3[128 * 3];
    __shared__ float b2s[C2];

    int tid = threadIdx.x;
    int p0  = blockIdx.x * 128;

    for (int i = tid; i < C2 * C1; i += 256) {
        int p = i >> 6, k = i & 63;
        w2t[k][p] = W2[i];
    }
    for (int i = tid; i < 128 * 3; i += 256) xs3[i] = x[p0 * 3 + i];
    if (tid < C2) b2s[tid] = b2[tid];
    __syncthreads();

    // h1 for 128 points
    for (int i = tid; i < 128 * C1; i += 256) {
        int q = i >> 6, c = i & 63;
        float v = fmaf(W1[c * 3 + 2], xs3[q * 3 + 2],
                  fmaf(W1[c * 3 + 1], xs3[q * 3 + 1],
                  fmaf(W1[c * 3 + 0], xs3[q * 3 + 0], b1[c])));
        h1s[q][c] = fmaxf(v, 0.f);
    }
    __syncthreads();

    int warp = tid >> 5, lane = tid & 31;
    int lane4 = lane * 4;
    float4 binit = *(const float4*)&b2s[lane4];

    for (int pass = 0; pass < 2; pass++) {
        int q0 = warp * 16 + pass * 8;     // 8 points this pass
        float4 acc[8];
        #pragma unroll
        for (int p = 0; p < 8; p++) acc[p] = binit;

        #pragma unroll 2
        for (int k = 0; k < C1; k += 4) {
            float4 w0 = *(const float4*)(w2t[k + 0] + lane4);
            float4 w1 = *(const float4*)(w2t[k + 1] + lane4);
            float4 w2 = *(const float4*)(w2t[k + 2] + lane4);
            float4 w3 = *(const float4*)(w2t[k + 3] + lane4);
            #pragma unroll
            for (int p = 0; p < 8; p++) {
                float4 h = *(const float4*)(h1s[q0 + p] + k);  // broadcast LDS
                float4 a = acc[p];
                a.x = fmaf(h.x, w0.x, a.x); a.y = fmaf(h.x, w0.y, a.y);
                a.z = fmaf(h.x, w0.z, a.z); a.w = fmaf(h.x, w0.w, a.w);
                a.x = fmaf(h.y, w1.x, a.x); a.y = fmaf(h.y, w1.y, a.y);
                a.z = fmaf(h.y, w1.z, a.z); a.w = fmaf(h.y, w1.w, a.w);
                a.x = fmaf(h.z, w2.x, a.x); a.y = fmaf(h.z, w2.y, a.y);
                a.z = fmaf(h.z, w2.z, a.z); a.w = fmaf(h.z, w2.w, a.w);
                a.x = fmaf(h.w, w3.x, a.x); a.y = fmaf(h.w, w3.y, a.y);
                a.z = fmaf(h.w, w3.z, a.z); a.w = fmaf(h.w, w3.w, a.w);
                acc[p] = a;
            }
        }

        #pragma unroll
        for (int p = 0; p < 8; p++) {
            float4 v = acc[p];
            __half2 h01 = __floats2half2_rn(fmaxf(v.x, 0.f), fmaxf(v.y, 0.f));
            __half2 h23 = __floats2half2_rn(fmaxf(v.z, 0.f), fmaxf(v.w, 0.f));
            uint2 st;
            st.x = *(unsigned*)&h01;
            st.y = *(unsigned*)&h23;
            ((uint2*)(g_fh + (size_t)(p0 + q0 + p) * C2))[lane] = st;
        }
    }
}

// ---------------------------------------------------------------------------
// Kernel 2: ball query + fp16 max-pool. Block = 8 warps, 8 centers of one
// batch (R2 structure, 2048 blocks). sq[] removed -> recomputed in-scan with
// the identical expression; smem 38.9 -> 29.3 KB raises occupancy to 6 blk/SM.
// ---------------------------------------------------------------------------
__global__ __launch_bounds__(256)
void group_max_kernel(const float* __restrict__ x, float* __restrict__ out)
{
    __shared__ float xs[NP], ys[NP], zs[NP];             // 24 KB
    __shared__ unsigned short nbr[8][NS];                // 1 KB
    __shared__ float tr[8][132];                         // padded transpose buf

    int b   = blockIdx.y;
    int tid = threadIdx.x;

    const float* xb = x + b * NP * 3;
    for (int i = tid; i < NP; i += 256) {
        xs[i] = xb[i * 3 + 0];
        ys[i] = xb[i * 3 + 1];
        zs[i] = xb[i * 3 + 2];
    }
    __syncthreads();

    int warp = tid >> 5, lane = tid & 31;
    int s = blockIdx.x * 8 + warp;

    float cx = xs[s], cy = ys[s], cz = zs[s];
    float cs = cx * cx + cy * cy + cz * cz;

    // Scan ascending j; first <=64 with dist <= R^2 (same expanded formula)
    int cnt = 0;
    for (int j0 = 0; j0 < NP && cnt < NS; j0 += 32) {
        int j = j0 + lane;
        float xj = xs[j], yj = ys[j], zj = zs[j];
        float sqj = xj * xj + yj * yj + zj * zj;
        float d = cs + sqj - 2.f * (cx * xj + cy * yj + cz * zj);
        bool ok = !(d > RAD2);
        unsigned mask = __ballot_sync(0xffffffffu, ok);
        int rank = __popc(mask & ((1u << lane) - 1u));
        if (ok && (cnt + rank) < NS)
            nbr[warp][cnt + rank] = (unsigned short)j;
        cnt += __popc(mask);
        if (cnt > NS) cnt = NS;
    }
    __syncwarp();

    // Max-pool fp16 f over neighbors: lane owns channels 4*lane..4*lane+3
    const uint2* fb = (const uint2*)(g_fh + (size_t)b * NP * C2);  // 32 uint2/row
    __half2 m0 = __float2half2_rn(0.f);
    __half2 m1 = m0;

    int k = 0;
    for (; k + 8 <= cnt; k += 8) {
        uint2 v[8];
        #pragma unroll
        for (int u = 0; u < 8; u++)
            v[u] = fb[(int)nbr[warp][k + u] * 32 + lane];
        #pragma unroll
        for (int u = 0; u < 8; u++) {
            m0 = __hmax2(m0, *reinterpret_cast<__half2*>(&v[u].x));
            m1 = __hmax2(m1, *reinterpret_cast<__half2*>(&v[u].y));
        }
    }
    for (; k < cnt; k++) {
        uint2 v = fb[(int)nbr[warp][k] * 32 + lane];
        m0 = __hmax2(m0, *reinterpret_cast<__half2*>(&v.x));
        m1 = __hmax2(m1, *reinterpret_cast<__half2*>(&v.y));
    }

    float2 f0 = __half22float2(m0);
    float2 f1 = __half22float2(m1);
    tr[warp][lane * 4 + 0] = f0.x;
    tr[warp][lane * 4 + 1] = f0.y;
    tr[warp][lane * 4 + 2] = f1.x;
    tr[warp][lane * 4 + 3] = f1.y;
    __syncthreads();

    float* ob = out + (size_t)b * C2 * NP + blockIdx.x * 8;
    for (int i = tid; i < C2 * 8; i += 256) {
        int si = i & 7;       // center within block
        int p  = i >> 3;      // channel
        ob[p * NP + si] = tr[si][p];
    }
}

extern "C" void kernel_launch(void* const* d_in, const int* in_sizes, int n_in,
                              void* d_out, int out_size)
{
    const float* x  = (const float*)d_in[0];
    const float* W1 = (const float*)d_in[1];
    const float* b1 = (const float*)d_in[2];
    const float* W2 = (const float*)d_in[3];
    const float* b2 = (const float*)d_in[4];
    float* out = (float*)d_out;

    // Kernel 1: 128 points per block -> 128 blocks
    mlp_kernel<<<(NB * NP) / 128, 256>>>(x, W1, b1, W2, b2);

    // Kernel 2: 8 centers per block, grid (256, 8)
    dim3 grid(NP / 8, NB);
    group_max_kernel<<<grid, 256>>>(x, out);
}

// round 8
// speedup vs baseline: 1.7763x; 1.0617x over previous
#include <cuda_runtime.h>
#include <cuda_fp16.h>

#define NB   8
#define NP   2048
#define C1   64
#define C2   128
#define NS   64
#define RAD2 0.36f

// Scratch: per-point MLP features f[b, n, 128] in fp16 (4 MB, L2-resident)
__device__ __half g_fh[NB * NP * C2];

// ---------------------------------------------------------------------------
// Kernel 1: per-point MLP (unchanged from R7 winner). Block = 256 threads /
// 128 points; W2 transposed in SMEM; warp accumulates 8 points per pass.
// ---------------------------------------------------------------------------
__global__ __launch_bounds__(256)
void mlp_kernel(const float* __restrict__ x,
                const float* __restrict__ W1,
                const float* __restrict__ b1,
                const float* __restrict__ W2,
                const float* __restrict__ b2)
{
    __shared__ float w2t[C1][C2];      // 32 KB, [k][p]
    __shared__ float h1s[128][C1];     // 32 KB
    __shared__ float xs3[128 * 3];
    __shared__ float b2s[C2];

    int tid = threadIdx.x;
    int p0  = blockIdx.x * 128;

    for (int i = tid; i < C2 * C1; i += 256) {
        int p = i >> 6, k = i & 63;
        w2t[k][p] = W2[i];
    }
    for (int i = tid; i < 128 * 3; i += 256) xs3[i] = x[p0 * 3 + i];
    if (tid < C2) b2s[tid] = b2[tid];
    __syncthreads();

    for (int i = tid; i < 128 * C1; i += 256) {
        int q = i >> 6, c = i & 63;
        float v = fmaf(W1[c * 3 + 2], xs3[q * 3 + 2],
                  fmaf(W1[c * 3 + 1], xs3[q * 3 + 1],
                  fmaf(W1[c * 3 + 0], xs3[q * 3 + 0], b1[c])));
        h1s[q][c] = fmaxf(v, 0.f);
    }
    __syncthreads();

    int warp = tid >> 5, lane = tid & 31;
    int lane4 = lane * 4;
    float4 binit = *(const float4*)&b2s[lane4];

    for (int pass = 0; pass < 2; pass++) {
        int q0 = warp * 16 + pass * 8;
        float4 acc[8];
        #pragma unroll
        for (int p = 0; p < 8; p++) acc[p] = binit;

        #pragma unroll 2
        for (int k = 0; k < C1; k += 4) {
            float4 w0 = *(const float4*)(w2t[k + 0] + lane4);
            float4 w1 = *(const float4*)(w2t[k + 1] + lane4);
            float4 w2 = *(const float4*)(w2t[k + 2] + lane4);
            float4 w3 = *(const float4*)(w2t[k + 3] + lane4);
            #pragma unroll
            for (int p = 0; p < 8; p++) {
                float4 h = *(const float4*)(h1s[q0 + p] + k);
                float4 a = acc[p];
                a.x = fmaf(h.x, w0.x, a.x); a.y = fmaf(h.x, w0.y, a.y);
                a.z = fmaf(h.x, w0.z, a.z); a.w = fmaf(h.x, w0.w, a.w);
                a.x = fmaf(h.y, w1.x, a.x); a.y = fmaf(h.y, w1.y, a.y);
                a.z = fmaf(h.y, w1.z, a.z); a.w = fmaf(h.y, w1.w, a.w);
                a.x = fmaf(h.z, w2.x, a.x); a.y = fmaf(h.z, w2.y, a.y);
                a.z = fmaf(h.z, w2.z, a.z); a.w = fmaf(h.z, w2.w, a.w);
                a.x = fmaf(h.w, w3.x, a.x); a.y = fmaf(h.w, w3.y, a.y);
                a.z = fmaf(h.w, w3.z, a.z); a.w = fmaf(h.w, w3.w, a.w);
                acc[p] = a;
            }
        }

        #pragma unroll
        for (int p = 0; p < 8; p++) {
            float4 v = acc[p];
            __half2 h01 = __floats2half2_rn(fmaxf(v.x, 0.f), fmaxf(v.y, 0.f));
            __half2 h23 = __floats2half2_rn(fmaxf(v.z, 0.f), fmaxf(v.w, 0.f));
            uint2 st;
            st.x = *(unsigned*)&h01;
            st.y = *(unsigned*)&h23;
            ((uint2*)(g_fh + (size_t)(p0 + q0 + p) * C2))[lane] = st;
        }
    }
}

// ---------------------------------------------------------------------------
// Kernel 2: ball query + fp16 max-pool. R7 winner structure (8 warps / 8
// centers / one batch per block, 2048 blocks, 30KB smem) with a leaner
// gather: 2 neighbors per warp LDG.128 (half-warp each covers a full 256B f
// row), 8 indices per LDS.128, shfl_xor(16) final merge.
// ---------------------------------------------------------------------------
__global__ __launch_bounds__(256, 6)
void group_max_kernel(const float* __restrict__ x, float* __restrict__ out)
{
    __shared__ float xs[NP], ys[NP], zs[NP];             // 24 KB
    __shared__ unsigned short nbr[8][NS];                // 1 KB
    __shared__ float tr[8][132];                         // padded transpose buf

    int b   = blockIdx.y;
    int tid = threadIdx.x;

    const float* xb = x + b * NP * 3;
    for (int i = tid; i < NP; i += 256) {
        xs[i] = xb[i * 3 + 0];
        ys[i] = xb[i * 3 + 1];
        zs[i] = xb[i * 3 + 2];
    }
    __syncthreads();

    int warp = tid >> 5, lane = tid & 31;
    int half = lane >> 4;      // which neighbor of a pair
    int lo   = lane & 15;      // 16B chunk within the 256B f row
    int s = blockIdx.x * 8 + warp;

    float cx = xs[s], cy = ys[s], cz = zs[s];
    float cs = cx * cx + cy * cy + cz * cz;

    // Scan ascending j; first <=64 with dist <= R^2 (same expanded formula)
    int cnt = 0;
    for (int j0 = 0; j0 < NP && cnt < NS; j0 += 32) {
        int j = j0 + lane;
        float xj = xs[j], yj = ys[j], zj = zs[j];
        float sqj = xj * xj + yj * yj + zj * zj;
        float d = cs + sqj - 2.f * (cx * xj + cy * yj + cz * zj);
        bool ok = !(d > RAD2);
        unsigned mask = __ballot_sync(0xffffffffu, ok);
        int rank = __popc(mask & ((1u << lane) - 1u));
        if (ok && (cnt + rank) < NS)
            nbr[warp][cnt + rank] = (unsigned short)j;
        cnt += __popc(mask);
        if (cnt > NS) cnt = NS;
    }
    __syncwarp();

    // Paired gather: lanes 0-15 -> even neighbor, lanes 16-31 -> odd neighbor
    const uint4* fb4 = (const uint4*)(g_fh + (size_t)b * NP * C2);  // 16 uint4/row
    __half2 m0 = __float2half2_rn(0.f);
    __half2 m1 = m0, m2 = m0, m3 = m0;

    int k = 0;
    for (; k + 8 <= cnt; k += 8) {
        uint4 nw = *(const uint4*)&nbr[warp][k];   // 8 ushort indices
        int j0 = half ? (int)(nw.x >> 16) : (int)(nw.x & 0xffffu);
        int j1 = half ? (int)(nw.y >> 16) : (int)(nw.y & 0xffffu);
        int j2 = half ? (int)(nw.z >> 16) : (int)(nw.z & 0xffffu);
        int j3 = half ? (int)(nw.w >> 16) : (int)(nw.w & 0xffffu);
        uint4 v0 = fb4[j0 * 16 + lo];
        uint4 v1 = fb4[j1 * 16 + lo];
        uint4 v2 = fb4[j2 * 16 + lo];
        uint4 v3 = fb4[j3 * 16 + lo];
        #define HM(v) \
            m0 = __hmax2(m0, *reinterpret_cast<__half2*>(&v.x)); \
            m1 = __hmax2(m1, *reinterpret_cast<__half2*>(&v.y)); \
            m2 = __hmax2(m2, *reinterpret_cast<__half2*>(&v.z)); \
            m3 = __hmax2(m3, *reinterpret_cast<__half2*>(&v.w));
        HM(v0) HM(v1) HM(v2) HM(v3)
    }
    for (; k < cnt; k += 2) {
        int idx = k + half;
        if (idx > cnt - 1) idx = cnt - 1;   // duplicate row = no-op for max
        int j = nbr[warp][idx];
        uint4 v = fb4[j * 16 + lo];
        HM(v)
    }
    #undef HM

    // Merge half-warp partials (each lo owns channels lo*8 .. lo*8+7)
    #define XMAX(m) { unsigned o = __shfl_xor_sync(0xffffffffu, *(unsigned*)&m, 16); \
                      m = __hmax2(m, *reinterpret_cast<__half2*>(&o)); }
    XMAX(m0) XMAX(m1) XMAX(m2) XMAX(m3)
    #undef XMAX

    if (half == 0) {
        float2 f0 = __half22float2(m0);
        float2 f1 = __half22float2(m1);
        float2 f2 = __half22float2(m2);
        float2 f3 = __half22float2(m3);
        float* t = &tr[warp][lo * 8];
        t[0] = f0.x; t[1] = f0.y; t[2] = f1.x; t[3] = f1.y;
        t[4] = f2.x; t[5] = f2.y; t[6] = f3.x; t[7] = f3.y;
    }
    __syncthreads();

    float* ob = out + (size_t)b * C2 * NP + blockIdx.x * 8;
    for (int i = tid; i < C2 * 8; i += 256) {
        int si = i & 7;       // center within block
        int p  = i >> 3;      // channel
        ob[p * NP + si] = tr[si][p];
    }
}

extern "C" void kernel_launch(void* const* d_in, const int* in_sizes, int n_in,
                              void* d_out, int out_size)
{
    const float* x  = (const float*)d_in[0];
    const float* W1 = (const float*)d_in[1];
    const float* b1 = (const float*)d_in[2];
    const float* W2 = (const float*)d_in[3];
    const float* b2 = (const float*)d_in[4];
    float* out = (float*)d_out;

    // Kernel 1: 128 points per block -> 128 blocks
    mlp_kernel<<<(NB * NP) / 128, 256>>>(x, W1, b1, W2, b2);

    // Kernel 2: 8 centers per block, grid (256, 8)
    dim3 grid(NP / 8, NB);
    group_max_kernel<<<grid, 256>>>(x, out);
}

// round 10
// speedup vs baseline: 1.8760x; 1.0561x over previous
#include <cuda_runtime.h>
#include <cuda_fp16.h>

#define NB   8
#define NP   2048
#define C1   64
#define C2   128
#define NS   64
#define RAD2 0.36f

// Scratch: per-point MLP features f[b, n, 128] in fp16 (4 MB, L2-resident)
__device__ __half g_fh[NB * NP * C2];

// ---------------------------------------------------------------------------
// Kernel 1: per-point MLP (unchanged R7 winner). Block = 256 threads /
// 128 points; W2 transposed in SMEM; warp accumulates 8 points per pass.
// ---------------------------------------------------------------------------
__global__ __launch_bounds__(256)
void mlp_kernel(const float* __restrict__ x,
                const float* __restrict__ W1,
                const float* __restrict__ b1,
                const float* __restrict__ W2,
                const float* __restrict__ b2)
{
    __shared__ float w2t[C1][C2];      // 32 KB, [k][p]
    __shared__ float h1s[128][C1];     // 32 KB
    __shared__ float xs3[128 * 3];
    __shared__ float b2s[C2];

    int tid = threadIdx.x;
    int p0  = blockIdx.x * 128;

    for (int i = tid; i < C2 * C1; i += 256) {
        int p = i >> 6, k = i & 63;
        w2t[k][p] = W2[i];
    }
    for (int i = tid; i < 128 * 3; i += 256) xs3[i] = x[p0 * 3 + i];
    if (tid < C2) b2s[tid] = b2[tid];
    __syncthreads();

    for (int i = tid; i < 128 * C1; i += 256) {
        int q = i >> 6, c = i & 63;
        float v = fmaf(W1[c * 3 + 2], xs3[q * 3 + 2],
                  fmaf(W1[c * 3 + 1], xs3[q * 3 + 1],
                  fmaf(W1[c * 3 + 0], xs3[q * 3 + 0], b1[c])));
        h1s[q][c] = fmaxf(v, 0.f);
    }
    __syncthreads();

    int warp = tid >> 5, lane = tid & 31;
    int lane4 = lane * 4;
    float4 binit = *(const float4*)&b2s[lane4];

    for (int pass = 0; pass < 2; pass++) {
        int q0 = warp * 16 + pass * 8;
        float4 acc[8];
        #pragma unroll
        for (int p = 0; p < 8; p++) acc[p] = binit;

        #pragma unroll 2
        for (int k = 0; k < C1; k += 4) {
            float4 w0 = *(const float4*)(w2t[k + 0] + lane4);
            float4 w1 = *(const float4*)(w2t[k + 1] + lane4);
            float4 w2 = *(const float4*)(w2t[k + 2] + lane4);
            float4 w3 = *(const float4*)(w2t[k + 3] + lane4);
            #pragma unroll
            for (int p = 0; p < 8; p++) {
                float4 h = *(const float4*)(h1s[q0 + p] + k);
                float4 a = acc[p];
                a.x = fmaf(h.x, w0.x, a.x); a.y = fmaf(h.x, w0.y, a.y);
                a.z = fmaf(h.x, w0.z, a.z); a.w = fmaf(h.x, w0.w, a.w);
                a.x = fmaf(h.y, w1.x, a.x); a.y = fmaf(h.y, w1.y, a.y);
                a.z = fmaf(h.y, w1.z, a.z); a.w = fmaf(h.y, w1.w, a.w);
                a.x = fmaf(h.z, w2.x, a.x); a.y = fmaf(h.z, w2.y, a.y);
                a.z = fmaf(h.z, w2.z, a.z); a.w = fmaf(h.z, w2.w, a.w);
                a.x = fmaf(h.w, w3.x, a.x); a.y = fmaf(h.w, w3.y, a.y);
                a.z = fmaf(h.w, w3.z, a.z); a.w = fmaf(h.w, w3.w, a.w);
                acc[p] = a;
            }
        }

        #pragma unroll
        for (int p = 0; p < 8; p++) {
            float4 v = acc[p];
            __half2 h01 = __floats2half2_rn(fmaxf(v.x, 0.f), fmaxf(v.y, 0.f));
            __half2 h23 = __floats2half2_rn(fmaxf(v.z, 0.f), fmaxf(v.w, 0.f));
            uint2 st;
            st.x = *(unsigned*)&h01;
            st.y = *(unsigned*)&h23;
            ((uint2*)(g_fh + (size_t)(p0 + q0 + p) * C2))[lane] = st;
        }
    }
}

// ---------------------------------------------------------------------------
// Kernel 2: ball query + fp16 max-pool. NO x staging: scan reads x straight
// from L2 (192 KB resident), killing the 24KB-per-block staging + barrier
// startup. smem 30 -> 5.3 KB. Scan handles 64 candidates/iter (2 loads in
// flight, 2 ballots). Gather/output identical to R8 winner.
// ---------------------------------------------------------------------------
__global__ __launch_bounds__(256, 6)
void group_max_kernel(const float* __restrict__ x, float* __restrict__ out)
{
    __shared__ unsigned short nbr[8][NS];                // 1 KB
    __shared__ float tr[8][132];                         // padded transpose buf

    int b   = blockIdx.y;
    int tid = threadIdx.x;
    int warp = tid >> 5, lane = tid & 31;
    int half = lane >> 4;      // which neighbor of a pair
    int lo   = lane & 15;      // 16B chunk within the 256B f row
    int s = blockIdx.x * 8 + warp;

    const float* xb = x + b * NP * 3;

    float cx = __ldg(&xb[s * 3 + 0]);
    float cy = __ldg(&xb[s * 3 + 1]);
    float cz = __ldg(&xb[s * 3 + 2]);
    float cs = cx * cx + cy * cy + cz * cz;

    // Scan ascending j, 64 candidates per iteration; first <=64 in-radius
    int cnt = 0;
    for (int j0 = 0; j0 < NP && cnt < NS; j0 += 64) {
        int ja = j0 + lane;
        int jb = ja + 32;
        float xa = __ldg(&xb[ja * 3 + 0]);
        float ya = __ldg(&xb[ja * 3 + 1]);
        float za = __ldg(&xb[ja * 3 + 2]);
        float xc = __ldg(&xb[jb * 3 + 0]);
        float yc = __ldg(&xb[jb * 3 + 1]);
        float zc = __ldg(&xb[jb * 3 + 2]);

        float sqa = xa * xa + ya * ya + za * za;
        float da  = cs + sqa - 2.f * (cx * xa + cy * ya + cz * za);
        bool oka = !(da > RAD2);
        unsigned ma = __ballot_sync(0xffffffffu, oka);
        int ra = __popc(ma & ((1u << lane) - 1u));
        if (oka && (cnt + ra) < NS)
            nbr[warp][cnt + ra] = (unsigned short)ja;
        cnt += __popc(ma);
        if (cnt > NS) cnt = NS;
        if (cnt >= NS) break;

        float sqb = xc * xc + yc * yc + zc * zc;
        float db  = cs + sqb - 2.f * (cx * xc + cy * yc + cz * zc);
        bool okb = !(db > RAD2);
        unsigned mb = __ballot_sync(0xffffffffu, okb);
        int rb = __popc(mb & ((1u << lane) - 1u));
        if (okb && (cnt + rb) < NS)
            nbr[warp][cnt + rb] = (unsigned short)jb;
        cnt += __popc(mb);
        if (cnt > NS) cnt = NS;
    }
    __syncwarp();

    // Paired gather: lanes 0-15 -> even neighbor, lanes 16-31 -> odd neighbor
    const uint4* fb4 = (const uint4*)(g_fh + (size_t)b * NP * C2);  // 16 uint4/row
    __half2 m0 = __float2half2_rn(0.f);
    __half2 m1 = m0, m2 = m0, m3 = m0;

    int k = 0;
    for (; k + 8 <= cnt; k += 8) {
        uint4 nw = *(const uint4*)&nbr[warp][k];   // 8 ushort indices
        int j0 = half ? (int)(nw.x >> 16) : (int)(nw.x & 0xffffu);
        int j1 = half ? (int)(nw.y >> 16) : (int)(nw.y & 0xffffu);
        int j2 = half ? (int)(nw.z >> 16) : (int)(nw.z & 0xffffu);
        int j3 = half ? (int)(nw.w >> 16) : (int)(nw.w & 0xffffu);
        uint4 v0 = fb4[j0 * 16 + lo];
        uint4 v1 = fb4[j1 * 16 + lo];
        uint4 v2 = fb4[j2 * 16 + lo];
        uint4 v3 = fb4[j3 * 16 + lo];
        #define HM(v) \
            m0 = __hmax2(m0, *reinterpret_cast<__half2*>(&v.x)); \
            m1 = __hmax2(m1, *reinterpret_cast<__half2*>(&v.y)); \
            m2 = __hmax2(m2, *reinterpret_cast<__half2*>(&v.z)); \
            m3 = __hmax2(m3, *reinterpret_cast<__half2*>(&v.w));
        HM(v0) HM(v1) HM(v2) HM(v3)
    }
    for (; k < cnt; k += 2) {
        int idx = k + half;
        if (idx > cnt - 1) idx = cnt - 1;   // duplicate row = no-op for max
        int j = nbr[warp][idx];
        uint4 v = fb4[j * 16 + lo];
        HM(v)
    }
    #undef HM

    // Merge half-warp partials (each lo owns channels lo*8 .. lo*8+7)
    #define XMAX(m) { unsigned o = __shfl_xor_sync(0xffffffffu, *(unsigned*)&m, 16); \
                      m = __hmax2(m, *reinterpret_cast<__half2*>(&o)); }
    XMAX(m0) XMAX(m1) XMAX(m2) XMAX(m3)
    #undef XMAX

    if (half == 0) {
        float2 f0 = __half22float2(m0);
        float2 f1 = __half22float2(m1);
        float2 f2 = __half22float2(m2);
        float2 f3 = __half22float2(m3);
        float* t = &tr[warp][lo * 8];
        t[0] = f0.x; t[1] = f0.y; t[2] = f1.x; t[3] = f1.y;
        t[4] = f2.x; t[5] = f2.y; t[6] = f3.x; t[7] = f3.y;
    }
    __syncthreads();

    float* ob = out + (size_t)b * C2 * NP + blockIdx.x * 8;
    for (int i = tid; i < C2 * 8; i += 256) {
        int si = i & 7;       // center within block
        int p  = i >> 3;      // channel
        ob[p * NP + si] = tr[si][p];
    }
}

extern "C" void kernel_launch(void* const* d_in, const int* in_sizes, int n_in,
                              void* d_out, int out_size)
{
    const float* x  = (const float*)d_in[0];
    const float* W1 = (const float*)d_in[1];
    const float* b1 = (const float*)d_in[2];
    const float* W2 = (const float*)d_in[3];
    const float* b2 = (const float*)d_in[4];
    float* out = (float*)d_out;

    // Kernel 1: 128 points per block -> 128 blocks
    mlp_kernel<<<(NB * NP) / 128, 256>>>(x, W1, b1, W2, b2);

    // Kernel 2: 8 centers per block, grid (256, 8)
    dim3 grid(NP / 8, NB);
    group_max_kernel<<<grid, 256>>>(x, out);
}